// round 5
// baseline (speedup 1.0000x reference)
#include <cuda_runtime.h>

// ---------------- problem constants ----------------
#define IMG   640
#define HW    (IMG*IMG)
#define Bc    2
#define Dc    96
#define HP    160
#define NTOK  (HP*HP)            // 25600 tokens per batch
#define TOK_ELEMS (Bc*NTOK*Dc)   // 4,915,200
#define LN_EPS 1e-5f

typedef unsigned long long ull;

// ---------------- scratch (device globals; no allocs allowed) ----------------
__device__ ull   g_wp [48*38];       // folded conv weights f32x2 do-pairs: [dp][38] taps 0..35, 36=b1, 37=pad
__device__ ull   g_w2p[3*48*16];     // second-conv weights, f32x2 do-pairs: [o][dp][tap]
__device__ float g_mx[Bc*NTOK];
__device__ float g_my[Bc*NTOK];
__device__ float g_s [Bc*NTOK];

// ---------------- helpers ----------------
__device__ __forceinline__ ull pk2(float v) {
    ull r; asm("mov.b64 %0, {%1, %1};" : "=l"(r) : "f"(v)); return r;
}
__device__ __forceinline__ ull pack2(float a, float b) {
    ull r; asm("mov.b64 %0, {%1, %2};" : "=l"(r) : "f"(a), "f"(b)); return r;
}
__device__ __forceinline__ void fma2(ull& acc, ull a, ull b) {
    asm("fma.rn.f32x2 %0, %1, %2, %0;" : "+l"(acc) : "l"(a), "l"(b));
}
__device__ __forceinline__ ull fma2_3(ull a, ull b, ull c) {
    ull r; asm("fma.rn.f32x2 %0, %1, %2, %3;" : "=l"(r) : "l"(a), "l"(b), "l"(c)); return r;
}
__device__ __forceinline__ ull mul2(ull a, ull b) {
    ull r; asm("mul.rn.f32x2 %0, %1, %2;" : "=l"(r) : "l"(a), "l"(b)); return r;
}
__device__ __forceinline__ ull add2(ull a, ull b) {
    ull r; asm("add.rn.f32x2 %0, %1, %2;" : "=l"(r) : "l"(a), "l"(b)); return r;
}
__device__ __forceinline__ float2 upk2(ull v) {
    float2 r; asm("mov.b64 {%0, %1}, %2;" : "=f"(r.x), "=f"(r.y) : "l"(v)); return r;
}

// ============================================================================
// Kernel A: fold embed (1x1) into the 3x3 conv -> w_eff over 4 channels.
// Warp-per-output (lane-parallel di, shfl reduce); tail repacks w2.
// ============================================================================
#define WEFF_WARP_BLOCKS 222   // 222*8 warps = 1776 = 48*37
__global__ void __launch_bounds__(256) k_weff(const float* __restrict__ ew,  // [96][3]
                                              const float* __restrict__ eb,  // [96]
                                              const float* __restrict__ w1,  // [96][96][3][3]
                                              const float* __restrict__ b1,  // [96]
                                              const float* __restrict__ w2)  // [3][96][4][4]
{
    const int bid = blockIdx.x;
    if (bid < WEFF_WARP_BLOCKS) {
        const int wid  = bid * 8 + (threadIdx.x >> 5);
        const int lane = threadIdx.x & 31;
        const int dp = wid / 37, t = wid % 37;
        if (t == 36) {
            if (lane == 0) g_wp[dp*38 + 36] = pack2(b1[2*dp], b1[2*dp+1]);
            if (lane == 1) g_wp[dp*38 + 37] = 0ULL;   // pad
            return;
        }
        const int c = t / 9, kk = t % 9;
        float v0 = 0.f, v1 = 0.f;
#pragma unroll
        for (int r = 0; r < 3; r++) {
            const int di = lane + 32*r;
            const float e = (c < 3) ? ew[di*3 + c] : eb[di];
            v0 = fmaf(w1[((2*dp    )*Dc + di)*9 + kk], e, v0);
            v1 = fmaf(w1[((2*dp + 1)*Dc + di)*9 + kk], e, v1);
        }
#pragma unroll
        for (int o = 16; o > 0; o >>= 1) {
            v0 += __shfl_xor_sync(0xFFFFFFFFu, v0, o);
            v1 += __shfl_xor_sync(0xFFFFFFFFu, v1, o);
        }
        if (lane == 0) g_wp[dp*38 + t] = pack2(v0, v1);
    } else {
        const int i = (bid - WEFF_WARP_BLOCKS) * 256 + threadIdx.x;
        if (i < 3*48*16) {
            const int tap = i & 15;
            const int dp  = (i >> 4) % 48;
            const int o   = i / (48*16);
            g_w2p[i] = pack2(w2[(o*Dc + 2*dp    )*16 + tap],
                             w2[(o*Dc + 2*dp + 1)*16 + tap]);
        }
    }
}

// ============================================================================
// Kernel B: fused conv3x3(4ch) + GELU + conv4x4-stride4 + transforms.
// Weights via LDS.128 (ull2); GELU as branch-free packed-f32x2 Taylor
// (6-term odd series of erf(v/sqrt2): abs err <2e-5 at |v|=1; |h| <~0.15).
// ============================================================================
__global__ void __launch_bounds__(256) k_fused(const float* __restrict__ x,
                                               const float* __restrict__ b2,
                                               float* __restrict__ out_scale)
{
    __shared__ float sx[4][18][20];          // [c][row][col] halo tile (+pad)
    __shared__ __align__(16) ull swp[48][38];// folded conv weight pairs (+bias,pad)
    __shared__ ull sw2p[3][48][16];          // second conv weight pairs

    const int tid = threadIdx.x;
    const int b   = blockIdx.z;
    const int X0  = blockIdx.x * 16;
    const int Y0  = blockIdx.y * 16;

    for (int i = tid; i < 4*18*18; i += 256) {
        const int c   = i / (18*18);
        const int r   = (i / 18) % 18;
        const int col = i % 18;
        const int gy = Y0 - 1 + r;
        const int gx = X0 - 1 + col;
        const bool in = ((unsigned)gy < (unsigned)IMG) && ((unsigned)gx < (unsigned)IMG);
        float v;
        if (c < 3) v = in ? x[((b*3 + c)*IMG + gy)*IMG + gx] : 0.f;
        else       v = in ? 1.f : 0.f;
        sx[c][r][col] = v;
    }
    for (int i = tid; i < 48*38;   i += 256) ((ull*)swp )[i] = g_wp[i];
    for (int i = tid; i < 3*48*16; i += 256) ((ull*)sw2p)[i] = g_w2p[i];
    __syncthreads();

    const int p   = tid >> 4;          // param within CTA (0..15)
    const int tap = tid & 15;          // position within 4x4 patch
    const int hy  = (p >> 2) * 4 + (tap >> 2);
    const int hx  = (p &  3) * 4 + (tap &  3);

    // register-cache the 4x3x3 input patch, pre-broadcast to f32x2
    ull xp2[36];
#pragma unroll
    for (int c = 0; c < 4; c++)
#pragma unroll
        for (int ky = 0; ky < 3; ky++)
#pragma unroll
            for (int kx = 0; kx < 3; kx++)
                xp2[c*9 + ky*3 + kx] = pk2(sx[c][hy + ky][hx + kx]);

    // packed gelu coefficients (hoisted)
    const ull C1 = pk2(-0.3333333333f);
    const ull C2 = pk2( 0.1f);
    const ull C3 = pk2(-0.0238095238f);
    const ull C4 = pk2( 0.0046296296f);
    const ull C5 = pk2(-7.5757576e-4f);
    const ull KS = pk2(0.7978845608f);   // sqrt(2/pi) = 1.1283792 * 0.70710678
    const ull KH = pk2(0.5f);
    const ull ONE = pk2(1.0f);

    ull pa0 = 0ULL, pa1 = 0ULL, pa2 = 0ULL;
#pragma unroll 2
    for (int dp = 0; dp < 48; dp++) {
        const ulonglong2* wrow = (const ulonglong2*)(&swp[dp][0]);
        ulonglong2 wb = wrow[18];        // (bias pair, pad)
        ull a0 = wb.x;
        ull a1 = 0ULL;
#pragma unroll
        for (int t = 0; t < 18; t++) {
            ulonglong2 w = wrow[t];
            fma2(a0, xp2[2*t],     w.x);
            fma2(a1, xp2[2*t + 1], w.y);
        }
        const ull hv = add2(a0, a1);     // packed (h0, h1)
        // gelu(v) = 0.5 v (1 + erf(v/sqrt2)); erf(v/sqrt2) = sqrt(2/pi)*v*poly(u), u=v^2/2
        const ull uu = mul2(mul2(hv, KH), hv);     // u = 0.5*v^2
        ull pp = fma2_3(uu, C5, C4);
        pp = fma2_3(uu, pp, C3);
        pp = fma2_3(uu, pp, C2);
        pp = fma2_3(uu, pp, C1);
        pp = fma2_3(uu, pp, ONE);                  // poly(u)
        const ull ev = mul2(mul2(hv, KS), pp);     // erf(v/sqrt2)
        const ull q  = mul2(hv, KH);               // 0.5 v
        const ull hp = fma2_3(q, ev, q);           // gelu(v) packed
        fma2(pa0, hp, sw2p[0][dp][tap]);
        fma2(pa1, hp, sw2p[1][dp][tap]);
        fma2(pa2, hp, sw2p[2][dp][tap]);
    }

    const float2 q0 = upk2(pa0), q1 = upk2(pa1), q2 = upk2(pa2);
    float p0 = q0.x + q0.y;
    float p1 = q1.x + q1.y;
    float p2 = q2.x + q2.y;
#pragma unroll
    for (int off = 8; off > 0; off >>= 1) {
        p0 += __shfl_down_sync(0xFFFFFFFFu, p0, off, 16);
        p1 += __shfl_down_sync(0xFFFFFFFFu, p1, off, 16);
        p2 += __shfl_down_sync(0xFFFFFFFFu, p2, off, 16);
    }
    if (tap == 0) {
        p0 += b2[0]; p1 += b2[1]; p2 += b2[2];
        const float mx = 2.0f * tanhf(p0);
        const float my = 2.0f * tanhf(p1);
        float s = expf(tanhf(p2));
        s = fminf(fmaxf(s, 0.5f), 2.0f);
        const int ppy = blockIdx.y * 4 + (p >> 2);
        const int ppx = blockIdx.x * 4 + (p &  3);
        const int n = (b*HP + ppy)*HP + ppx;
        g_mx[n] = mx; g_my[n] = my; g_s[n] = s;
        out_scale[n] = s;
    }
}

// ============================================================================
// Kernel C: deformable sampling + mean + embed + LayerNorm.
// Two tokens per warp; all 32 lanes gather; width-16 reduces.
// ============================================================================
__global__ void __launch_bounds__(256) k_sample(const float* __restrict__ x,
                                                const float* __restrict__ ew,
                                                const float* __restrict__ eb,
                                                const float* __restrict__ lnw,
                                                const float* __restrict__ lnb,
                                                float* __restrict__ out_tokens)
{
    const int warp = (blockIdx.x * 256 + threadIdx.x) >> 5;
    const int lane = threadIdx.x & 31;
    const int half = lane >> 4;
    const int hl   = lane & 15;
    const int n_g  = warp * 2 + half;
    if (n_g >= Bc*NTOK) return;
    const int b  = n_g / NTOK;
    const int n  = n_g % NTOK;
    const int py = n / HP;
    const int px = n % HP;

    const float mx = g_mx[n_g], my = g_my[n_g], s = g_s[n_g];
    const float cx = px*4 + 2.0f;
    const float cy = py*4 + 2.0f;
    const float halfw = s * 2.0f;

    const float x1 = fminf(fmaxf(cx + mx - halfw, 0.0f), 639.0f);
    const float x2 = fminf(fmaxf(cx + mx + halfw, 0.0f), 639.0f);
    const float y1 = fminf(fmaxf(cy + my - halfw, 0.0f), 639.0f);
    const float y2 = fminf(fmaxf(cy + my + halfw, 0.0f), 639.0f);

    const int i = hl & 3;
    const int j = hl >> 2;
    const float xt = x1 + (x2 - x1) * (i * (1.0f/3.0f));
    const float yt = y1 + (y2 - y1) * (j * (1.0f/3.0f));
    const float xf = floorf(xt), yf = floorf(yt);
    const float wx = xt - xf,   wy = yt - yf;
    int X0i = min(max((int)xf, 0), IMG-1);
    int X1i = min(X0i + 1, IMG-1);
    int Y0i = min(max((int)yf, 0), IMG-1);
    int Y1i = min(Y0i + 1, IMG-1);
    const float w00 = (1.f-wx)*(1.f-wy), w01 = wx*(1.f-wy);
    const float w10 = (1.f-wx)*wy,       w11 = wx*wy;
    const float* xb = x + b*3*HW;

    float m0, m1, m2;
#pragma unroll
    for (int c = 0; c < 3; c++) {
        const float* f = xb + c*HW;
        float v = f[Y0i*IMG + X0i]*w00 + f[Y0i*IMG + X1i]*w01
                + f[Y1i*IMG + X0i]*w10 + f[Y1i*IMG + X1i]*w11;
        if (c == 0) m0 = v; else if (c == 1) m1 = v; else m2 = v;
    }
#pragma unroll
    for (int o = 8; o > 0; o >>= 1) {
        m0 += __shfl_xor_sync(0xFFFFFFFFu, m0, o);
        m1 += __shfl_xor_sync(0xFFFFFFFFu, m1, o);
        m2 += __shfl_xor_sync(0xFFFFFFFFu, m2, o);
    }
    m0 *= (1.0f/16.0f); m1 *= (1.0f/16.0f); m2 *= (1.0f/16.0f);

    float t[6];
    float lsum = 0.f;
#pragma unroll
    for (int r = 0; r < 6; r++) {
        int d = hl + 16*r;
        t[r] = ew[d*3+0]*m0 + ew[d*3+1]*m1 + ew[d*3+2]*m2 + eb[d];
        lsum += t[r];
    }
#pragma unroll
    for (int o = 8; o > 0; o >>= 1) lsum += __shfl_xor_sync(0xFFFFFFFFu, lsum, o);
    const float mu = lsum * (1.0f/96.0f);
    float lsq = 0.f;
#pragma unroll
    for (int r = 0; r < 6; r++) { float d = t[r]-mu; lsq += d*d; }
#pragma unroll
    for (int o = 8; o > 0; o >>= 1) lsq += __shfl_xor_sync(0xFFFFFFFFu, lsq, o);
    const float var = lsq * (1.0f/96.0f);
    const float inv = 1.0f / sqrtf(var + LN_EPS);

    float* outw = out_tokens + (size_t)n_g*Dc;
#pragma unroll
    for (int r = 0; r < 6; r++) {
        int d = hl + 16*r;
        outw[d] = (t[r] - mu) * inv * lnw[d] + lnb[d];
    }
}

// ============================================================================
extern "C" void kernel_launch(void* const* d_in, const int* in_sizes, int n_in,
                              void* d_out, int out_size) {
    const float* x   = (const float*)d_in[0];
    const float* ew  = (const float*)d_in[1];
    const float* eb  = (const float*)d_in[2];
    const float* w1  = (const float*)d_in[3];
    const float* b1  = (const float*)d_in[4];
    const float* w2  = (const float*)d_in[5];
    const float* b2  = (const float*)d_in[6];
    const float* lnw = (const float*)d_in[7];
    const float* lnb = (const float*)d_in[8];
    float* out = (float*)d_out;

    float* out_tokens = out;
    float* out_scale  = out + TOK_ELEMS;

    k_weff<<<WEFF_WARP_BLOCKS + 9, 256>>>(ew, eb, w1, b1, w2);

    dim3 gfused(IMG/16, IMG/16, Bc);     // 40 x 40 x 2
    k_fused<<<gfused, 256>>>(x, b2, out_scale);

    k_sample<<<(Bc*NTOK/2*32 + 255)/256, 256>>>(x, ew, eb, lnw, lnb, out_tokens);
}

// round 7
// speedup vs baseline: 1.2455x; 1.2455x over previous
#include <cuda_runtime.h>
#include <cstdint>

// ---------------- problem constants ----------------
#define IMG   640
#define HW    (IMG*IMG)
#define Bc    2
#define Dc    96
#define HP    160
#define NTOK  (HP*HP)            // 25600 tokens per batch
#define TOK_ELEMS (Bc*NTOK*Dc)   // 4,915,200
#define LN_EPS 1e-5f

#define KPAD  40                 // 36 taps + bias col + 3 zero pad
#define NT    12                 // n-tiles of 8 (96 outputs)
#define KS    5                  // k-steps of 8 (40)

typedef unsigned long long ull;

// ---------------- scratch (device globals; zero-initialized, no allocs) -----
__device__ float  g_wB[Dc*KPAD];        // folded conv weights [do][k] (tf32-rounded; pads stay 0)
__device__ float2 g_bfrag[NT*KS*32];    // B fragments in m16n8k8 lane layout
__device__ ull    g_w2p[3*48*16];       // second-conv weights f32x2 do-pairs [o][dp][tap]
__device__ float  g_mx[Bc*NTOK];
__device__ float  g_my[Bc*NTOK];
__device__ float  g_s [Bc*NTOK];

// ---------------- helpers ----------------
__device__ __forceinline__ ull pk2(float v) {
    ull r; asm("mov.b64 %0, {%1, %1};" : "=l"(r) : "f"(v)); return r;
}
__device__ __forceinline__ ull pack2(float a, float b) {
    ull r; asm("mov.b64 %0, {%1, %2};" : "=l"(r) : "f"(a), "f"(b)); return r;
}
__device__ __forceinline__ void fma2(ull& acc, ull a, ull b) {
    asm("fma.rn.f32x2 %0, %1, %2, %0;" : "+l"(acc) : "l"(a), "l"(b));
}
__device__ __forceinline__ ull fma2_3(ull a, ull b, ull c) {
    ull r; asm("fma.rn.f32x2 %0, %1, %2, %3;" : "=l"(r) : "l"(a), "l"(b), "l"(c)); return r;
}
__device__ __forceinline__ ull mul2(ull a, ull b) {
    ull r; asm("mul.rn.f32x2 %0, %1, %2;" : "=l"(r) : "l"(a), "l"(b)); return r;
}
__device__ __forceinline__ float2 upk2(ull v) {
    float2 r; asm("mov.b64 {%0, %1}, %2;" : "=f"(r.x), "=f"(r.y) : "l"(v)); return r;
}
__device__ __forceinline__ float tf32r(float v) {
    uint32_t o; asm("cvt.rna.tf32.f32 %0, %1;" : "=r"(o) : "f"(v));
    return __uint_as_float(o);
}
__device__ __forceinline__ uint32_t tf32b(float v) {
    uint32_t o; asm("cvt.rna.tf32.f32 %0, %1;" : "=r"(o) : "f"(v));
    return o;
}
// packed branch-free GELU: erf(v/sqrt2) odd Taylor (|h| << 1 here; err <2e-5 @|v|=1)
__device__ __forceinline__ ull gelu2(ull hv, ull C1, ull C2, ull C3,
                                     ull KSc, ull KH, ull ONE) {
    const ull uu = mul2(mul2(hv, KH), hv);   // u = v^2/2
    ull pp = fma2_3(uu, C3, C2);
    pp = fma2_3(uu, pp, C1);
    pp = fma2_3(uu, pp, ONE);
    const ull ev = mul2(mul2(hv, KSc), pp);  // erf(v/sqrt2)
    const ull q  = mul2(hv, KH);
    return fma2_3(q, ev, q);                 // 0.5v(1+erf)
}

// ============================================================================
// Kernel A: fold embed (1x1) + b1 into w_eff [96][40] (tf32-rounded);
// repack w2 into f32x2 do-pairs. Warp-per-output, lane-parallel di.
// ============================================================================
#define WEFF_WARP_BLOCKS 444   // 444*8 = 3552 = 96*37 warps
__global__ void __launch_bounds__(256) k_weff(const float* __restrict__ ew,  // [96][3]
                                              const float* __restrict__ eb,  // [96]
                                              const float* __restrict__ w1,  // [96][96][3][3]
                                              const float* __restrict__ b1,  // [96]
                                              const float* __restrict__ w2)  // [3][96][4][4]
{
    const int bid = blockIdx.x;
    if (bid < WEFF_WARP_BLOCKS) {
        const int wid  = bid * 8 + (threadIdx.x >> 5);
        const int lane = threadIdx.x & 31;
        const int dd = wid / 37, t = wid % 37;
        if (t == 36) {
            if (lane == 0) g_wB[dd*KPAD + 36] = tf32r(b1[dd]);
            if (lane < 3)  g_wB[dd*KPAD + 37 + lane] = 0.f;   // explicit K pad
            return;
        }
        const int c = t / 9, kk = t % 9;
        float v = 0.f;
#pragma unroll
        for (int r = 0; r < 3; r++) {
            const int di = lane + 32*r;
            const float e = (c < 3) ? ew[di*3 + c] : eb[di];
            v = fmaf(w1[(dd*Dc + di)*9 + kk], e, v);
        }
#pragma unroll
        for (int o = 16; o > 0; o >>= 1) v += __shfl_xor_sync(0xFFFFFFFFu, v, o);
        if (lane == 0) g_wB[dd*KPAD + t] = tf32r(v);
    } else {
        const int i = (bid - WEFF_WARP_BLOCKS) * 256 + threadIdx.x;
        if (i < 3*48*16) {
            const int tap = i & 15;
            const int dp  = (i >> 4) % 48;
            const int o   = i / (48*16);
            g_w2p[i] = pack2(w2[(o*Dc + 2*dp    )*16 + tap],
                             w2[(o*Dc + 2*dp + 1)*16 + tap]);
        }
    }
}

// ============================================================================
// Kernel A2: pack B fragments for mma.sync m16n8k8 (row.col):
// lane holds b0 = B[k = ks*8 + lane%4][n = nt*8 + lane/4], b1 = same with k+4.
// (B col-major = our K-major weight rows wB[n][k].)
// ============================================================================
__global__ void __launch_bounds__(256) k_pack() {
    const int i = blockIdx.x * 256 + threadIdx.x;
    if (i < NT*KS*32) {
        const int lane = i & 31;
        const int ks   = (i >> 5) % KS;
        const int nt   = i / (KS*32);
        const int n = nt*8 + (lane >> 2);
        const int k = ks*8 + (lane & 3);
        g_bfrag[i] = make_float2(g_wB[n*KPAD + k], g_wB[n*KPAD + k + 4]);
    }
}

// ============================================================================
// Kernel B: fused conv3x3(4ch+bias col) via mma.sync tf32 + GELU +
// conv4x4-stride4 + tanh/exp transforms.
// CTA = 16x8 pixels = 8 patches; warp w = patch (w&3, w>>2); 16 pixels = M16.
// ============================================================================
__global__ void __launch_bounds__(256) k_fused_mma(const float* __restrict__ x,
                                                   const float* __restrict__ b2,
                                                   float* __restrict__ out_scale)
{
    __shared__ float  sx[4*10*20];          // halo tile [c][row][col], 20-col pitch
    __shared__ float2 sbf[NT*KS*32];        // B fragments
    __shared__ ull    sw2[3*48*16];         // w2 do-pairs

    const int tid  = threadIdx.x;
    const int w    = tid >> 5;
    const int lane = tid & 31;
    const int g    = lane >> 2;             // group id: pixel rows g, g+8
    const int tq   = lane & 3;              // thread-in-group: k offset / col pair
    const int b    = blockIdx.z;
    const int X0   = blockIdx.x * 16;
    const int Y0   = blockIdx.y * 8;

    // stage halo tile (rows Y0-1..Y0+8, cols X0-1..X0+16), 3 channels + ones
    for (int i = tid; i < 4*10*18; i += 256) {
        const int c   = i / 180;
        const int rem = i % 180;
        const int r   = rem / 18;
        const int col = rem % 18;
        const int gy = Y0 - 1 + r;
        const int gx = X0 - 1 + col;
        const bool in = ((unsigned)gy < (unsigned)IMG) && ((unsigned)gx < (unsigned)IMG);
        float v;
        if (c < 3) v = in ? x[((b*3 + c)*IMG + gy)*IMG + gx] : 0.f;
        else       v = in ? 1.f : 0.f;
        sx[(c*10 + r)*20 + col] = v;
    }
    for (int i = tid; i < NT*KS*32; i += 256) sbf[i] = g_bfrag[i];
    for (int i = tid; i < 3*48*16;  i += 256) sw2[i] = g_w2p[i];
    __syncthreads();

    // patch origin for this warp
    const int hx0 = (w & 3) * 4;
    const int hy0 = (w >> 2) * 4;
    // pixel rows handled by this thread: r = g (tap g) and r+8 (tap g+8)
    const int hxA = hx0 + (g & 3),        hyA = hy0 + (g >> 2);        // pixel g
    const int hxB = hx0 + ((g + 8) & 3),  hyB = hy0 + ((g + 8) >> 2);  // pixel g+8

    // A fragments: a[ks][0..3] = A[g][k], A[g+8][k], A[g][k+4], A[g+8][k+4], k=ks*8+tq
    uint32_t afr[KS][4];
#pragma unroll
    for (int ks = 0; ks < KS; ks++) {
#pragma unroll
        for (int h = 0; h < 2; h++) {
            const int k = ks*8 + tq + h*4;
            float vA, vB;
            if (k < 36) {
                const int c  = k / 9;
                const int kk = k % 9;
                const int dy = kk / 3, dx = kk % 3;
                vA = sx[(c*10 + hyA + dy)*20 + hxA + dx];
                vB = sx[(c*10 + hyB + dy)*20 + hxB + dx];
            } else if (k == 36) { vA = 1.f; vB = 1.f; }
            else                { vA = 0.f; vB = 0.f; }
            afr[ks][2*h]     = tf32b(vA);
            afr[ks][2*h + 1] = tf32b(vB);
        }
    }

    // 12 n-tiles x 5 k-steps of m16n8k8 tf32 MMA
    float c0[NT], c1[NT], c2[NT], c3[NT];
#pragma unroll
    for (int nt = 0; nt < NT; nt++) { c0[nt]=0.f; c1[nt]=0.f; c2[nt]=0.f; c3[nt]=0.f; }
#pragma unroll
    for (int nt = 0; nt < NT; nt++) {
#pragma unroll
        for (int ks = 0; ks < KS; ks++) {
            const float2 bf = sbf[(nt*KS + ks)*32 + lane];
            const uint32_t b0 = __float_as_uint(bf.x);
            const uint32_t b1r = __float_as_uint(bf.y);
            asm volatile(
                "mma.sync.aligned.m16n8k8.row.col.f32.tf32.tf32.f32 "
                "{%0,%1,%2,%3}, {%4,%5,%6,%7}, {%8,%9}, {%0,%1,%2,%3};"
                : "+f"(c0[nt]), "+f"(c1[nt]), "+f"(c2[nt]), "+f"(c3[nt])
                : "r"(afr[ks][0]), "r"(afr[ks][1]), "r"(afr[ks][2]), "r"(afr[ks][3]),
                  "r"(b0), "r"(b1r));
        }
    }

    // epilogue: gelu + w2 contraction.
    // (c0,c1) = pixel g cols (nt*8+tq*2, +1); (c2,c3) = pixel g+8 same cols.
    const ull C1c = pk2(-0.3333333333f);
    const ull C2c = pk2( 0.1f);
    const ull C3c = pk2(-0.0238095238f);
    const ull KSc = pk2( 0.7978845608f);
    const ull KHc = pk2( 0.5f);
    const ull ONE = pk2( 1.0f);
    const int tapA = g, tapB = g + 8;

    ull pa0 = 0ULL, pa1 = 0ULL, pa2 = 0ULL;
#pragma unroll
    for (int nt = 0; nt < NT; nt++) {
        const int dp = nt*4 + tq;                 // do-pair index of cols (nt*8+tq*2, +1)
        const ull hA = gelu2(pack2(c0[nt], c1[nt]), C1c, C2c, C3c, KSc, KHc, ONE);
        const ull hB = gelu2(pack2(c2[nt], c3[nt]), C1c, C2c, C3c, KSc, KHc, ONE);
        fma2(pa0, hA, sw2[(0*48 + dp)*16 + tapA]);
        fma2(pa0, hB, sw2[(0*48 + dp)*16 + tapB]);
        fma2(pa1, hA, sw2[(1*48 + dp)*16 + tapA]);
        fma2(pa1, hB, sw2[(1*48 + dp)*16 + tapB]);
        fma2(pa2, hA, sw2[(2*48 + dp)*16 + tapA]);
        fma2(pa2, hB, sw2[(2*48 + dp)*16 + tapB]);
    }

    const float2 q0 = upk2(pa0), q1 = upk2(pa1), q2 = upk2(pa2);
    float p0 = q0.x + q0.y;
    float p1 = q1.x + q1.y;
    float p2 = q2.x + q2.y;
    // full-warp sum = sum over 16 pixels x 96 channels of this patch
#pragma unroll
    for (int o = 16; o > 0; o >>= 1) {
        p0 += __shfl_xor_sync(0xFFFFFFFFu, p0, o);
        p1 += __shfl_xor_sync(0xFFFFFFFFu, p1, o);
        p2 += __shfl_xor_sync(0xFFFFFFFFu, p2, o);
    }
    if (lane == 0) {
        p0 += b2[0]; p1 += b2[1]; p2 += b2[2];
        const float mx = 2.0f * tanhf(p0);
        const float my = 2.0f * tanhf(p1);
        float s = expf(tanhf(p2));
        s = fminf(fmaxf(s, 0.5f), 2.0f);
        const int ppy = blockIdx.y*2 + (w >> 2);
        const int ppx = blockIdx.x*4 + (w & 3);
        const int n = (b*HP + ppy)*HP + ppx;
        g_mx[n] = mx; g_my[n] = my; g_s[n] = s;
        out_scale[n] = s;
    }
}

// ============================================================================
// Kernel C: deformable sampling + mean + embed + LayerNorm.
// mean(bilerp(embed(x))) == embed(mean(bilerp(x))) by linearity/convexity.
// Two tokens per warp; width-16 reduces.
// ============================================================================
__global__ void __launch_bounds__(256) k_sample(const float* __restrict__ x,
                                                const float* __restrict__ ew,
                                                const float* __restrict__ eb,
                                                const float* __restrict__ lnw,
                                                const float* __restrict__ lnb,
                                                float* __restrict__ out_tokens)
{
    const int warp = (blockIdx.x * 256 + threadIdx.x) >> 5;
    const int lane = threadIdx.x & 31;
    const int half = lane >> 4;
    const int hl   = lane & 15;
    const int n_g  = warp * 2 + half;
    if (n_g >= Bc*NTOK) return;
    const int b  = n_g / NTOK;
    const int n  = n_g % NTOK;
    const int py = n / HP;
    const int px = n % HP;

    const float mx = g_mx[n_g], my = g_my[n_g], s = g_s[n_g];
    const float cx = px*4 + 2.0f;
    const float cy = py*4 + 2.0f;
    const float halfw = s * 2.0f;

    const float x1 = fminf(fmaxf(cx + mx - halfw, 0.0f), 639.0f);
    const float x2 = fminf(fmaxf(cx + mx + halfw, 0.0f), 639.0f);
    const float y1 = fminf(fmaxf(cy + my - halfw, 0.0f), 639.0f);
    const float y2 = fminf(fmaxf(cy + my + halfw, 0.0f), 639.0f);

    const int i = hl & 3;
    const int j = hl >> 2;
    const float xt = x1 + (x2 - x1) * (i * (1.0f/3.0f));
    const float yt = y1 + (y2 - y1) * (j * (1.0f/3.0f));
    const float xf = floorf(xt), yf = floorf(yt);
    const float wx = xt - xf,   wy = yt - yf;
    int X0i = min(max((int)xf, 0), IMG-1);
    int X1i = min(X0i + 1, IMG-1);
    int Y0i = min(max((int)yf, 0), IMG-1);
    int Y1i = min(Y0i + 1, IMG-1);
    const float w00 = (1.f-wx)*(1.f-wy), w01 = wx*(1.f-wy);
    const float w10 = (1.f-wx)*wy,       w11 = wx*wy;
    const float* xb = x + b*3*HW;

    float m0, m1, m2;
#pragma unroll
    for (int c = 0; c < 3; c++) {
        const float* f = xb + c*HW;
        float v = f[Y0i*IMG + X0i]*w00 + f[Y0i*IMG + X1i]*w01
                + f[Y1i*IMG + X0i]*w10 + f[Y1i*IMG + X1i]*w11;
        if (c == 0) m0 = v; else if (c == 1) m1 = v; else m2 = v;
    }
#pragma unroll
    for (int o = 8; o > 0; o >>= 1) {
        m0 += __shfl_xor_sync(0xFFFFFFFFu, m0, o);
        m1 += __shfl_xor_sync(0xFFFFFFFFu, m1, o);
        m2 += __shfl_xor_sync(0xFFFFFFFFu, m2, o);
    }
    m0 *= (1.0f/16.0f); m1 *= (1.0f/16.0f); m2 *= (1.0f/16.0f);

    float t[6];
    float lsum = 0.f;
#pragma unroll
    for (int r = 0; r < 6; r++) {
        int d = hl + 16*r;
        t[r] = ew[d*3+0]*m0 + ew[d*3+1]*m1 + ew[d*3+2]*m2 + eb[d];
        lsum += t[r];
    }
#pragma unroll
    for (int o = 8; o > 0; o >>= 1) lsum += __shfl_xor_sync(0xFFFFFFFFu, lsum, o);
    const float mu = lsum * (1.0f/96.0f);
    float lsq = 0.f;
#pragma unroll
    for (int r = 0; r < 6; r++) { float d = t[r]-mu; lsq += d*d; }
#pragma unroll
    for (int o = 8; o > 0; o >>= 1) lsq += __shfl_xor_sync(0xFFFFFFFFu, lsq, o);
    const float var = lsq * (1.0f/96.0f);
    const float inv = 1.0f / sqrtf(var + LN_EPS);

    float* outw = out_tokens + (size_t)n_g*Dc;
#pragma unroll
    for (int r = 0; r < 6; r++) {
        int d = hl + 16*r;
        outw[d] = (t[r] - mu) * inv * lnw[d] + lnb[d];
    }
}

// ============================================================================
extern "C" void kernel_launch(void* const* d_in, const int* in_sizes, int n_in,
                              void* d_out, int out_size) {
    const float* x   = (const float*)d_in[0];
    const float* ew  = (const float*)d_in[1];
    const float* eb  = (const float*)d_in[2];
    const float* w1  = (const float*)d_in[3];
    const float* b1  = (const float*)d_in[4];
    const float* w2  = (const float*)d_in[5];
    const float* b2  = (const float*)d_in[6];
    const float* lnw = (const float*)d_in[7];
    const float* lnb = (const float*)d_in[8];
    float* out = (float*)d_out;

    float* out_tokens = out;
    float* out_scale  = out + TOK_ELEMS;

    k_weff<<<WEFF_WARP_BLOCKS + 9, 256>>>(ew, eb, w1, b1, w2);
    k_pack<<<8, 256>>>();

    dim3 gfused(IMG/16, IMG/8, Bc);      // 40 x 80 x 2
    k_fused_mma<<<gfused, 256>>>(x, b2, out_scale);

    k_sample<<<(Bc*NTOK/2*32 + 255)/256, 256>>>(x, ew, eb, lnw, lnb, out_tokens);
}

// round 8
// speedup vs baseline: 1.3733x; 1.1026x over previous
#include <cuda_runtime.h>
#include <cstdint>

// ---------------- problem constants ----------------
#define IMG   640
#define HW    (IMG*IMG)
#define Bc    2
#define Dc    96
#define HP    160
#define NTOK  (HP*HP)            // 25600 tokens per batch
#define TOK_ELEMS (Bc*NTOK*Dc)   // 4,915,200
#define LN_EPS 1e-5f

#define KPAD  48                 // 36 taps + bias col + 11 zero pad (3 k-steps of 16)
#define NT    12                 // n-tiles of 8 (96 outputs)
#define KS    3                  // k-steps of 16

typedef unsigned long long ull;

// ---------------- scratch (device globals; zero-initialized, no allocs) -----
__device__ float g_wB[Dc*KPAD];      // folded conv weights [do][k] (f32; pads 0)
__device__ uint2 g_bfrag[NT*KS*32];  // B fragments (bf16x2 pairs) in m16n8k16 lane layout
__device__ ull   g_w2p[3*48*16];     // second-conv weights f32x2 do-pairs [o][dp][tap]
__device__ float g_mx[Bc*NTOK];
__device__ float g_my[Bc*NTOK];
__device__ float g_s [Bc*NTOK];

// ---------------- helpers ----------------
__device__ __forceinline__ ull pk2(float v) {
    ull r; asm("mov.b64 %0, {%1, %1};" : "=l"(r) : "f"(v)); return r;
}
__device__ __forceinline__ ull pack2(float a, float b) {
    ull r; asm("mov.b64 %0, {%1, %2};" : "=l"(r) : "f"(a), "f"(b)); return r;
}
__device__ __forceinline__ void fma2(ull& acc, ull a, ull b) {
    asm("fma.rn.f32x2 %0, %1, %2, %0;" : "+l"(acc) : "l"(a), "l"(b));
}
__device__ __forceinline__ ull fma2_3(ull a, ull b, ull c) {
    ull r; asm("fma.rn.f32x2 %0, %1, %2, %3;" : "=l"(r) : "l"(a), "l"(b), "l"(c)); return r;
}
__device__ __forceinline__ ull mul2(ull a, ull b) {
    ull r; asm("mul.rn.f32x2 %0, %1, %2;" : "=l"(r) : "l"(a), "l"(b)); return r;
}
__device__ __forceinline__ float2 upk2(ull v) {
    float2 r; asm("mov.b64 {%0, %1}, %2;" : "=f"(r.x), "=f"(r.y) : "l"(v)); return r;
}
// pack two floats into bf16x2: low half = lo, high half = hi
__device__ __forceinline__ uint32_t bf2(float lo, float hi) {
    uint32_t r; asm("cvt.rn.bf16x2.f32 %0, %1, %2;" : "=r"(r) : "f"(hi), "f"(lo));
    return r;
}
// packed branch-free GELU: erf(v/sqrt2) odd Taylor (|h| << 1 here; err <2e-5 @|v|=1)
__device__ __forceinline__ ull gelu2(ull hv, ull C1, ull C2, ull C3,
                                     ull KSc, ull KH, ull ONE) {
    const ull uu = mul2(mul2(hv, KH), hv);   // u = v^2/2
    ull pp = fma2_3(uu, C3, C2);
    pp = fma2_3(uu, pp, C1);
    pp = fma2_3(uu, pp, ONE);
    const ull ev = mul2(mul2(hv, KSc), pp);  // erf(v/sqrt2)
    const ull q  = mul2(hv, KH);
    return fma2_3(q, ev, q);                 // 0.5v(1+erf)
}

// ============================================================================
// Kernel A: fold embed (1x1) + b1 into w_eff [96][48]; repack w2.
// Warp-per-output, lane-parallel di reduction.
// ============================================================================
#define WEFF_WARP_BLOCKS 444   // 444*8 = 3552 = 96*37 warps
__global__ void __launch_bounds__(256) k_weff(const float* __restrict__ ew,  // [96][3]
                                              const float* __restrict__ eb,  // [96]
                                              const float* __restrict__ w1,  // [96][96][3][3]
                                              const float* __restrict__ b1,  // [96]
                                              const float* __restrict__ w2)  // [3][96][4][4]
{
    const int bid = blockIdx.x;
    if (bid < WEFF_WARP_BLOCKS) {
        const int wid  = bid * 8 + (threadIdx.x >> 5);
        const int lane = threadIdx.x & 31;
        const int dd = wid / 37, t = wid % 37;
        if (t == 36) {
            if (lane == 0) g_wB[dd*KPAD + 36] = b1[dd];
            if (lane >= 1 && lane <= 11) g_wB[dd*KPAD + 36 + lane] = 0.f;  // pads 37..47
            return;
        }
        const int c = t / 9, kk = t % 9;
        float v = 0.f;
#pragma unroll
        for (int r = 0; r < 3; r++) {
            const int di = lane + 32*r;
            const float e = (c < 3) ? ew[di*3 + c] : eb[di];
            v = fmaf(w1[(dd*Dc + di)*9 + kk], e, v);
        }
#pragma unroll
        for (int o = 16; o > 0; o >>= 1) v += __shfl_xor_sync(0xFFFFFFFFu, v, o);
        if (lane == 0) g_wB[dd*KPAD + t] = v;
    } else {
        const int i = (bid - WEFF_WARP_BLOCKS) * 256 + threadIdx.x;
        if (i < 3*48*16) {
            const int tap = i & 15;
            const int dp  = (i >> 4) % 48;
            const int o   = i / (48*16);
            g_w2p[i] = pack2(w2[(o*Dc + 2*dp    )*16 + tap],
                             w2[(o*Dc + 2*dp + 1)*16 + tap]);
        }
    }
}

// ============================================================================
// Kernel A2: pack B fragments for mma.sync m16n8k16 bf16 (row.col):
// lane holds b0 = {B[k0][n], B[k0+1][n]}, b1 = {B[k0+8][n], B[k0+9][n]}
// with n = nt*8 + lane/4, k0 = ks*16 + (lane%4)*2. (B col-major = wB[n][k].)
// ============================================================================
__global__ void __launch_bounds__(256) k_pack() {
    const int i = blockIdx.x * 256 + threadIdx.x;
    if (i < NT*KS*32) {
        const int lane = i & 31;
        const int ks   = (i >> 5) % KS;
        const int nt   = i / (KS*32);
        const int n  = nt*8 + (lane >> 2);
        const int k0 = ks*16 + (lane & 3)*2;
        uint2 r;
        r.x = bf2(g_wB[n*KPAD + k0    ], g_wB[n*KPAD + k0 + 1]);
        r.y = bf2(g_wB[n*KPAD + k0 + 8], g_wB[n*KPAD + k0 + 9]);
        g_bfrag[i] = r;
    }
}

// ============================================================================
// Kernel B: fused conv3x3(4ch+bias col) via mma.sync bf16 m16n8k16 + GELU +
// conv4x4-stride4 + tanh/exp transforms.
// CTA = 16x8 pixels = 8 patches; warp w = one patch (16 pixels = M16).
// Per-n-tile accumulate->epilogue keeps only 4 accum regs live.
// ============================================================================
__global__ void __launch_bounds__(256) k_fused_mma(const float* __restrict__ x,
                                                   const float* __restrict__ b2,
                                                   float* __restrict__ out_scale)
{
    __shared__ float sx[4*10*20];           // halo tile [c][row][col], 20-col pitch
    __shared__ uint2 sbf[NT*KS*32];         // B fragments
    __shared__ ull   sw2[3*48*16];          // w2 do-pairs

    const int tid  = threadIdx.x;
    const int w    = tid >> 5;
    const int lane = tid & 31;
    const int g    = lane >> 2;             // group id: pixel rows g, g+8
    const int tq   = lane & 3;              // thread-in-group: k/col-pair selector
    const int b    = blockIdx.z;
    const int X0   = blockIdx.x * 16;
    const int Y0   = blockIdx.y * 8;

    // stage halo tile (rows Y0-1..Y0+8, cols X0-1..X0+16), 3 channels + ones
    for (int i = tid; i < 4*10*18; i += 256) {
        const int c   = i / 180;
        const int rem = i % 180;
        const int r   = rem / 18;
        const int col = rem % 18;
        const int gy = Y0 - 1 + r;
        const int gx = X0 - 1 + col;
        const bool in = ((unsigned)gy < (unsigned)IMG) && ((unsigned)gx < (unsigned)IMG);
        float v;
        if (c < 3) v = in ? x[((b*3 + c)*IMG + gy)*IMG + gx] : 0.f;
        else       v = in ? 1.f : 0.f;
        sx[(c*10 + r)*20 + col] = v;
    }
    for (int i = tid; i < NT*KS*32; i += 256) sbf[i] = g_bfrag[i];
    for (int i = tid; i < 3*48*16;  i += 256) sw2[i] = g_w2p[i];
    __syncthreads();

    // patch origin for this warp
    const int hx0 = (w & 3) * 4;
    const int hy0 = (w >> 2) * 4;
    // two pixels handled by this thread (rows g and g+8 of the M16 strip)
    const int hxA = hx0 + (g & 3),        hyA = hy0 + (g >> 2);
    const int hxB = hx0 + ((g + 8) & 3),  hyB = hy0 + ((g + 8) >> 2);

    auto sval = [&](int k, int hx, int hy) -> float {
        if (k < 36) {
            const int c  = k / 9;
            const int kk = k % 9;
            return sx[(c*10 + hy + kk/3)*20 + hx + kk%3];
        }
        return (k == 36) ? 1.f : 0.f;
    };

    // A fragments (bf16): afr[ks] = {rowA k-pair, rowB k-pair, rowA k+8 pair, rowB k+8 pair}
    uint32_t afr[KS][4];
#pragma unroll
    for (int ks = 0; ks < KS; ks++) {
#pragma unroll
        for (int h = 0; h < 2; h++) {
            const int k0 = ks*16 + 2*tq + h*8;
            afr[ks][2*h]     = bf2(sval(k0, hxA, hyA), sval(k0+1, hxA, hyA));
            afr[ks][2*h + 1] = bf2(sval(k0, hxB, hyB), sval(k0+1, hxB, hyB));
        }
    }

    // packed gelu coefficients
    const ull C1c = pk2(-0.3333333333f);
    const ull C2c = pk2( 0.1f);
    const ull C3c = pk2(-0.0238095238f);
    const ull KSc = pk2( 0.7978845608f);
    const ull KHc = pk2( 0.5f);
    const ull ONE = pk2( 1.0f);
    const int tapA = g, tapB = g + 8;

    ull pa0 = 0ULL, pa1 = 0ULL, pa2 = 0ULL;
#pragma unroll
    for (int nt = 0; nt < NT; nt++) {
        float c0 = 0.f, c1 = 0.f, c2 = 0.f, c3 = 0.f;
#pragma unroll
        for (int ks = 0; ks < KS; ks++) {
            const uint2 bf = sbf[(nt*KS + ks)*32 + lane];
            asm volatile(
                "mma.sync.aligned.m16n8k16.row.col.f32.bf16.bf16.f32 "
                "{%0,%1,%2,%3}, {%4,%5,%6,%7}, {%8,%9}, {%0,%1,%2,%3};"
                : "+f"(c0), "+f"(c1), "+f"(c2), "+f"(c3)
                : "r"(afr[ks][0]), "r"(afr[ks][1]), "r"(afr[ks][2]), "r"(afr[ks][3]),
                  "r"(bf.x), "r"(bf.y));
        }
        // epilogue for this n-tile: (c0,c1)=pixel A cols (nt*8+2tq, +1); (c2,c3)=pixel B
        const int dp = nt*4 + tq;
        const ull hA = gelu2(pack2(c0, c1), C1c, C2c, C3c, KSc, KHc, ONE);
        const ull hB = gelu2(pack2(c2, c3), C1c, C2c, C3c, KSc, KHc, ONE);
        fma2(pa0, hA, sw2[(0*48 + dp)*16 + tapA]);
        fma2(pa0, hB, sw2[(0*48 + dp)*16 + tapB]);
        fma2(pa1, hA, sw2[(1*48 + dp)*16 + tapA]);
        fma2(pa1, hB, sw2[(1*48 + dp)*16 + tapB]);
        fma2(pa2, hA, sw2[(2*48 + dp)*16 + tapA]);
        fma2(pa2, hB, sw2[(2*48 + dp)*16 + tapB]);
    }

    const float2 q0 = upk2(pa0), q1 = upk2(pa1), q2 = upk2(pa2);
    float p0 = q0.x + q0.y;
    float p1 = q1.x + q1.y;
    float p2 = q2.x + q2.y;
    // full-warp sum = sum over 16 pixels x 96 channels of this patch
#pragma unroll
    for (int o = 16; o > 0; o >>= 1) {
        p0 += __shfl_xor_sync(0xFFFFFFFFu, p0, o);
        p1 += __shfl_xor_sync(0xFFFFFFFFu, p1, o);
        p2 += __shfl_xor_sync(0xFFFFFFFFu, p2, o);
    }
    if (lane == 0) {
        p0 += b2[0]; p1 += b2[1]; p2 += b2[2];
        const float mx = 2.0f * tanhf(p0);
        const float my = 2.0f * tanhf(p1);
        float s = expf(tanhf(p2));
        s = fminf(fmaxf(s, 0.5f), 2.0f);
        const int ppy = blockIdx.y*2 + (w >> 2);
        const int ppx = blockIdx.x*4 + (w & 3);
        const int n = (b*HP + ppy)*HP + ppx;
        g_mx[n] = mx; g_my[n] = my; g_s[n] = s;
        out_scale[n] = s;
    }
}

// ============================================================================
// Kernel C: deformable sampling + mean + embed + LayerNorm.
// mean(bilerp(embed(x))) == embed(mean(bilerp(x))) by linearity/convexity.
// Two tokens per warp; width-16 reduces.
// ============================================================================
__global__ void __launch_bounds__(256) k_sample(const float* __restrict__ x,
                                                const float* __restrict__ ew,
                                                const float* __restrict__ eb,
                                                const float* __restrict__ lnw,
                                                const float* __restrict__ lnb,
                                                float* __restrict__ out_tokens)
{
    const int warp = (blockIdx.x * 256 + threadIdx.x) >> 5;
    const int lane = threadIdx.x & 31;
    const int half = lane >> 4;
    const int hl   = lane & 15;
    const int n_g  = warp * 2 + half;
    if (n_g >= Bc*NTOK) return;
    const int b  = n_g / NTOK;
    const int n  = n_g % NTOK;
    const int py = n / HP;
    const int px = n % HP;

    const float mx = g_mx[n_g], my = g_my[n_g], s = g_s[n_g];
    const float cx = px*4 + 2.0f;
    const float cy = py*4 + 2.0f;
    const float halfw = s * 2.0f;

    const float x1 = fminf(fmaxf(cx + mx - halfw, 0.0f), 639.0f);
    const float x2 = fminf(fmaxf(cx + mx + halfw, 0.0f), 639.0f);
    const float y1 = fminf(fmaxf(cy + my - halfw, 0.0f), 639.0f);
    const float y2 = fminf(fmaxf(cy + my + halfw, 0.0f), 639.0f);

    const int i = hl & 3;
    const int j = hl >> 2;
    const float xt = x1 + (x2 - x1) * (i * (1.0f/3.0f));
    const float yt = y1 + (y2 - y1) * (j * (1.0f/3.0f));
    const float xf = floorf(xt), yf = floorf(yt);
    const float wx = xt - xf,   wy = yt - yf;
    int X0i = min(max((int)xf, 0), IMG-1);
    int X1i = min(X0i + 1, IMG-1);
    int Y0i = min(max((int)yf, 0), IMG-1);
    int Y1i = min(Y0i + 1, IMG-1);
    const float w00 = (1.f-wx)*(1.f-wy), w01 = wx*(1.f-wy);
    const float w10 = (1.f-wx)*wy,       w11 = wx*wy;
    const float* xb = x + b*3*HW;

    float m0, m1, m2;
#pragma unroll
    for (int c = 0; c < 3; c++) {
        const float* f = xb + c*HW;
        float v = f[Y0i*IMG + X0i]*w00 + f[Y0i*IMG + X1i]*w01
                + f[Y1i*IMG + X0i]*w10 + f[Y1i*IMG + X1i]*w11;
        if (c == 0) m0 = v; else if (c == 1) m1 = v; else m2 = v;
    }
#pragma unroll
    for (int o = 8; o > 0; o >>= 1) {
        m0 += __shfl_xor_sync(0xFFFFFFFFu, m0, o);
        m1 += __shfl_xor_sync(0xFFFFFFFFu, m1, o);
        m2 += __shfl_xor_sync(0xFFFFFFFFu, m2, o);
    }
    m0 *= (1.0f/16.0f); m1 *= (1.0f/16.0f); m2 *= (1.0f/16.0f);

    float t[6];
    float lsum = 0.f;
#pragma unroll
    for (int r = 0; r < 6; r++) {
        int d = hl + 16*r;
        t[r] = ew[d*3+0]*m0 + ew[d*3+1]*m1 + ew[d*3+2]*m2 + eb[d];
        lsum += t[r];
    }
#pragma unroll
    for (int o = 8; o > 0; o >>= 1) lsum += __shfl_xor_sync(0xFFFFFFFFu, lsum, o);
    const float mu = lsum * (1.0f/96.0f);
    float lsq = 0.f;
#pragma unroll
    for (int r = 0; r < 6; r++) { float d = t[r]-mu; lsq += d*d; }
#pragma unroll
    for (int o = 8; o > 0; o >>= 1) lsq += __shfl_xor_sync(0xFFFFFFFFu, lsq, o);
    const float var = lsq * (1.0f/96.0f);
    const float inv = 1.0f / sqrtf(var + LN_EPS);

    float* outw = out_tokens + (size_t)n_g*Dc;
#pragma unroll
    for (int r = 0; r < 6; r++) {
        int d = hl + 16*r;
        outw[d] = (t[r] - mu) * inv * lnw[d] + lnb[d];
    }
}

// ============================================================================
extern "C" void kernel_launch(void* const* d_in, const int* in_sizes, int n_in,
                              void* d_out, int out_size) {
    const float* x   = (const float*)d_in[0];
    const float* ew  = (const float*)d_in[1];
    const float* eb  = (const float*)d_in[2];
    const float* w1  = (const float*)d_in[3];
    const float* b1  = (const float*)d_in[4];
    const float* w2  = (const float*)d_in[5];
    const float* b2  = (const float*)d_in[6];
    const float* lnw = (const float*)d_in[7];
    const float* lnb = (const float*)d_in[8];
    float* out = (float*)d_out;

    float* out_tokens = out;
    float* out_scale  = out + TOK_ELEMS;

    k_weff<<<WEFF_WARP_BLOCKS + 9, 256>>>(ew, eb, w1, b1, w2);
    k_pack<<<5, 256>>>();

    dim3 gfused(IMG/16, IMG/8, Bc);      // 40 x 80 x 2
    k_fused_mma<<<gfused, 256>>>(x, b2, out_scale);

    k_sample<<<(Bc*NTOK/2*32 + 255)/256, 256>>>(x, ew, eb, lnw, lnb, out_tokens);
}